// round 15
// baseline (speedup 1.0000x reference)
#include <cuda_runtime.h>
#include <cuda_fp16.h>
#include <math.h>
#include <stdint.h>

#define Bb 128
#define Cc 512
#define Pp 196
#define Tt 32
#define Vv 10403
#define Ee 128
#define Uu 256
#define Gg 1024      // 4*U
#define Kcat 896     // C + E + U

#define Vpad 10496   // 82 * 128
#define NCH 28       // Kcat / 32 k-chunks

// packed fp32x2 FMA
#define FMA2(d, a, b) asm("fma.rn.f32x2 %0, %1, %2, %0;" : "+l"(d) : "l"(a), "l"(b))
#define PACK2(d, x)   asm("mov.b64 %0, {%1, %1};" : "=l"(d) : "f"(x))

__device__ __forceinline__ uint32_t smem_to_u32(const void* p) {
    uint32_t a;
    asm("{ .reg .u64 t; cvta.to.shared.u64 t, %1; cvt.u32.u64 %0, t; }" : "=r"(a) : "l"(p));
    return a;
}
__device__ __forceinline__ void ldsm4(uint32_t& r0, uint32_t& r1, uint32_t& r2, uint32_t& r3,
                                      uint32_t addr) {
    asm volatile("ldmatrix.sync.aligned.m8n8.x4.shared.b16 {%0,%1,%2,%3}, [%4];"
                 : "=r"(r0), "=r"(r1), "=r"(r2), "=r"(r3) : "r"(addr));
}
__device__ __forceinline__ void mma16816(float* d, const uint32_t* a, const uint32_t* b) {
    asm volatile("mma.sync.aligned.m16n8k16.row.col.f32.f16.f16.f32 "
                 "{%0,%1,%2,%3}, {%4,%5,%6,%7}, {%8,%9}, {%0,%1,%2,%3};"
                 : "+f"(d[0]), "+f"(d[1]), "+f"(d[2]), "+f"(d[3])
                 : "r"(a[0]), "r"(a[1]), "r"(a[2]), "r"(a[3]), "r"(b[0]), "r"(b[1]));
}
#define CP_ASYNC16(sm, g) \
    asm volatile("cp.async.cg.shared.global [%0], [%1], 16;" :: "r"(sm), "l"(g))
#define CP_COMMIT() asm volatile("cp.async.commit_group;")
#define CP_WAIT2()  asm volatile("cp.async.wait_group 2;")

// ---------------- scratch (device globals) -------------------------------------
__device__ float g_mean[Bb*Cc];
__device__ float g_keys[Bb*Pp*Uu];       // [B,P,U]
__device__ float g_xemb[Bb*Tt*Ee];       // [B,T,E]
__device__ float g_h[Bb*Uu];
__device__ float g_c[Bb*Uu];
__device__ float g_q[Bb*Uu];
__device__ float g_gates[Bb*Gg];
__device__ float g_attn[Bb*Tt*Cc];       // [B,T,C]
// A matrix in r' = t*128 + b order, fp16, filled by producers (no convA pass)
__device__ __half g_Ah[(size_t)Bb*Tt*Kcat];   // [4096, 896]
__device__ __half g_Bh[(size_t)Vpad*Kcat];    // [10496, 896]

// ---------------- mean over spatial positions -----------------------------------
__global__ void mean_kernel(const float* __restrict__ img) {
    int row  = blockIdx.x * 8 + (threadIdx.x >> 5);
    int lane = threadIdx.x & 31;
    const float* src = img + (size_t)row * Pp;
    float s = 0.f;
    for (int p = lane; p < Pp; p += 32) s += src[p];
    #pragma unroll
    for (int o = 16; o > 0; o >>= 1) s += __shfl_down_sync(0xffffffffu, s, o);
    if (lane == 0) g_mean[row] = s * (1.0f / 196.0f);
}

// ---------------- h0 / c0 init ---------------------------------------------------
__global__ void hc0_kernel(const float* __restrict__ Wh0, const float* __restrict__ bh0,
                           const float* __restrict__ Wc0, const float* __restrict__ bc0) {
    __shared__ float mf[Cc];
    int b = blockIdx.x, tid = threadIdx.x;
    mf[tid]       = g_mean[b*Cc + tid];
    mf[tid + 256] = g_mean[b*Cc + 256 + tid];
    __syncthreads();
    int u = tid;
    const float* wh = Wh0 + (size_t)u * Cc;
    const float* wc = Wc0 + (size_t)u * Cc;
    float ah = 0.f, ac = 0.f;
    #pragma unroll 4
    for (int c = 0; c < Cc; c++) { ah += mf[c]*wh[c]; ac += mf[c]*wc[c]; }
    float h0 = ah + bh0[u];
    float c0 = ac + bc0[u];
    g_h[b*Uu + u] = h0;
    g_c[b*Uu + u] = c0;
    g_q[b*Uu + u] = c0;
}

// ---------------- embedding gather -----------------------------------------------
__global__ void emb_kernel(const int* __restrict__ ix, const float* __restrict__ emb) {
    int idx = blockIdx.x * 256 + threadIdx.x;
    int r = idx >> 7, e = idx & 127;
    g_xemb[idx] = emb[(size_t)ix[r] * Ee + e];
}

// ---------------- emb segment of A (fp16), all 4096 rows --------------------------
__global__ void embh_kernel() {
    int idx = blockIdx.x * 256 + threadIdx.x;
    int rp = idx >> 7, e = idx & 127;           // rp = t*128 + b
    int t = rp >> 7, b = rp & 127;
    g_Ah[(size_t)rp * Kcat + Cc + e] = __float2half(g_xemb[(b*Tt + t)*Ee + e]);
}

// ---------------- Wout -> fp16, padded rows zero ----------------------------------
__global__ void convB_kernel(const float* __restrict__ Wout) {
    int v = blockIdx.x;
    int tid = threadIdx.x;
    __half* dst = g_Bh + (size_t)v * Kcat;
    if (v < Vv) {
        const float* src = Wout + (size_t)v * Kcat;
        for (int k = tid; k < Kcat; k += 256) dst[k] = __float2half(src[k]);
    } else {
        for (int k = tid; k < Kcat; k += 256) dst[k] = __float2half(0.f);
    }
}

// ---------------- keys[b,p,u] -----------------------------------------------------
__global__ void keys_kernel(const float* __restrict__ Wk, const float* __restrict__ bk,
                            const float* __restrict__ img) {
    int b  = blockIdx.z;
    int n0 = blockIdx.x * 64;   // u
    int m0 = blockIdx.y * 64;   // p
    __shared__ __align__(16) float sA[16][68];
    __shared__ __align__(16) float sB[16][68];
    int tid = threadIdx.x;
    int tx = tid & 15, ty = tid >> 4;
    unsigned long long accp[4][2] = {};
    const float* imgb = img + (size_t)b * Cc * Pp;
    for (int k0 = 0; k0 < Cc; k0 += 16) {
        {
            int k = tid >> 4, mg = tid & 15;
            int p = m0 + mg*4;
            float4 v = make_float4(0.f,0.f,0.f,0.f);
            if (p < Pp) v = *(const float4*)&imgb[(size_t)(k0+k)*Pp + p];
            *(float4*)&sA[k][mg*4] = v;
        }
        {
            int nn = tid & 63, kg = tid >> 6;
            float4 v = *(const float4*)&Wk[(size_t)(n0+nn)*Cc + k0 + kg*4];
            sB[kg*4+0][nn] = v.x; sB[kg*4+1][nn] = v.y;
            sB[kg*4+2][nn] = v.z; sB[kg*4+3][nn] = v.w;
        }
        __syncthreads();
        #pragma unroll
        for (int kk = 0; kk < 16; kk++) {
            float4 a4 = *(const float4*)&sA[kk][ty*4];
            ulonglong2 b2 = *(const ulonglong2*)&sB[kk][tx*4];
            float av[4] = {a4.x, a4.y, a4.z, a4.w};
            #pragma unroll
            for (int i = 0; i < 4; i++) {
                unsigned long long ap; PACK2(ap, av[i]);
                FMA2(accp[i][0], ap, b2.x);
                FMA2(accp[i][1], ap, b2.y);
            }
        }
        __syncthreads();
    }
    #pragma unroll
    for (int i = 0; i < 4; i++) {
        int p = m0 + ty*4 + i;
        if (p >= Pp) continue;
        float* orow = g_keys + ((size_t)b*Pp + p)*Uu;
        #pragma unroll
        for (int j = 0; j < 2; j++) {
            float2 f = *(float2*)&accp[i][j];
            int u = n0 + tx*4 + j*2;
            orow[u]   = f.x + bk[u];
            orow[u+1] = f.y + bk[u+1];
        }
    }
}

// ---------------- per-step: lstm(t-1) + attention (writes fp16 A segments) --------
__global__ void attn_kernel(int t, const float* __restrict__ img, float* __restrict__ maps) {
    int b = blockIdx.x, tid = threadIdx.x;
    __shared__ float qs[Uu];
    __shared__ float sc[256];
    __shared__ float ws[256];
    float q;
    if (t == 0) {
        q = g_q[b*Uu + tid];
    } else {
        const float* g = g_gates + b*Gg;
        float ig = g[tid], fg = g[tid+256], gg = g[tid+512], og = g[tid+768];
        float si = 1.f / (1.f + expf(-ig));
        float sf = 1.f / (1.f + expf(-fg));
        float so = 1.f / (1.f + expf(-og));
        float cn = sf * g_c[b*Uu + tid] + si * tanhf(gg);
        float hn = so * tanhf(cn);
        g_c[b*Uu + tid] = cn;
        g_h[b*Uu + tid] = hn;
        g_Ah[(size_t)((t-1)*Bb + b)*Kcat + (Cc + Ee) + tid] = __float2half(hn);
        q = hn;
    }
    qs[tid] = q;
    __syncthreads();
    float s = -INFINITY;
    if (tid < Pp) {
        const float4* kb = (const float4*)(g_keys + ((size_t)b*Pp + tid)*Uu);
        float acc = 0.f;
        #pragma unroll 8
        for (int u4 = 0; u4 < Uu/4; u4++) {
            float4 kv = kb[u4];
            float4 qv = *(const float4*)&qs[u4*4];
            acc += kv.x*qv.x + kv.y*qv.y + kv.z*qv.z + kv.w*qv.w;
        }
        s = acc * 0.0625f;
    }
    sc[tid] = s;
    __syncthreads();
    for (int o = 128; o > 0; o >>= 1) {
        if (tid < o) sc[tid] = fmaxf(sc[tid], sc[tid+o]);
        __syncthreads();
    }
    float mx = sc[0];
    __syncthreads();
    float ex = (tid < Pp) ? expf(s - mx) : 0.f;
    sc[tid] = ex;
    __syncthreads();
    for (int o = 128; o > 0; o >>= 1) {
        if (tid < o) sc[tid] += sc[tid+o];
        __syncthreads();
    }
    float inv = 1.f / sc[0];
    float w = ex * inv;
    ws[tid] = w;
    if (tid < Pp) maps[((size_t)b*Tt + t)*Pp + tid] = w;
    __syncthreads();
    // weighted sum: thread tid owns channels tid and tid+256
    {
        const float* r0 = img + ((size_t)b*Cc + tid)*Pp;
        const float* r1 = r0 + 256*(size_t)Pp;
        float a0 = 0.f, a1 = 0.f;
        #pragma unroll 7
        for (int p = 0; p < Pp; p += 4) {
            float4 w4 = *(const float4*)&ws[p];
            float4 x0 = *(const float4*)&r0[p];
            float4 x1 = *(const float4*)&r1[p];
            a0 += w4.x*x0.x + w4.y*x0.y + w4.z*x0.z + w4.w*x0.w;
            a1 += w4.x*x1.x + w4.y*x1.y + w4.z*x1.z + w4.w*x1.w;
        }
        float* arow = g_attn + ((size_t)b*Tt + t)*Cc;
        arow[tid]       = a0;
        arow[tid + 256] = a1;
        __half* ah = g_Ah + (size_t)(t*Bb + b)*Kcat;
        ah[tid]       = __float2half(a0);
        ah[tid + 256] = __float2half(a1);
    }
}

// ---------------- per-step gates GEMM ---------------------------------------------
__global__ void gates_kernel(int t, const float* __restrict__ Wih, const float* __restrict__ bih,
                             const float* __restrict__ Whh, const float* __restrict__ bhh) {
    int n0 = blockIdx.x * 64;
    int m0 = blockIdx.y * 16;
    __shared__ __align__(16) float sA[32][16];
    __shared__ float sB[64][33];
    int tid = threadIdx.x;
    int n  = tid & 63;
    int mB = (tid >> 6) * 4;
    unsigned long long accp[2] = {};
    for (int k0 = 0; k0 < Kcat; k0 += 32) {
        #pragma unroll
        for (int i = 0; i < 2; i++) {
            int id = tid + i*256;
            int mm = id & 15, k = (id >> 4) & 31;
            int gk = k0 + k, bb = m0 + mm;
            float v;
            if (gk < Ee)            v = g_xemb[(bb*Tt + t)*Ee + gk];
            else if (gk < Ee + Cc)  v = g_attn[((size_t)bb*Tt + t)*Cc + (gk - Ee)];
            else                    v = g_h[bb*Uu + (gk - Ee - Cc)];
            sA[k][mm] = v;
        }
        #pragma unroll
        for (int i = 0; i < 8; i++) {
            int id = tid + i*256;
            int nn = id >> 5, k = id & 31;
            int gk = k0 + k, j = n0 + nn;
            sB[nn][k] = (gk < Ee + Cc) ? Wih[(size_t)j*(Ee+Cc) + gk]
                                       : Whh[(size_t)j*Uu + (gk - Ee - Cc)];
        }
        __syncthreads();
        #pragma unroll
        for (int kk = 0; kk < 32; kk++) {
            ulonglong2 ap2 = *(const ulonglong2*)&sA[kk][mB];
            float bv = sB[n][kk];
            unsigned long long bp; PACK2(bp, bv);
            FMA2(accp[0], ap2.x, bp);
            FMA2(accp[1], ap2.y, bp);
        }
        __syncthreads();
    }
    int j = n0 + n;
    float bias = bih[j] + bhh[j];
    float2 f0 = *(float2*)&accp[0];
    float2 f1 = *(float2*)&accp[1];
    g_gates[(m0 + mB + 0)*Gg + j] = f0.x + bias;
    g_gates[(m0 + mB + 1)*Gg + j] = f0.y + bias;
    g_gates[(m0 + mB + 2)*Gg + j] = f1.x + bias;
    g_gates[(m0 + mB + 3)*Gg + j] = f1.y + bias;
}

// ---------------- final LSTM update (h_31, fp16 straight into A) -------------------
__global__ void lstm_last_kernel() {
    int b = blockIdx.x, u = threadIdx.x;
    const float* g = g_gates + b*Gg;
    float ig = g[u], fg = g[u+256], gg = g[u+512], og = g[u+768];
    float si = 1.f / (1.f + expf(-ig));
    float sf = 1.f / (1.f + expf(-fg));
    float so = 1.f / (1.f + expf(-og));
    float cn = sf * g_c[b*Uu + u] + si * tanhf(gg);
    float hn = so * tanhf(cn);
    g_Ah[(size_t)((Tt-1)*Bb + b)*Kcat + (Cc + Ee) + u] = __float2half(hn);
}

// ---------------- HMMA fp16 logits GEMM: CTA tile 64x128, short-residence CTAs ----
// D[r', v] = Ah[r', 896] @ Bh[Vpad, 896]^T;  r' = t*128 + b.
// 8 warps as 2(m) x 4(n); warp tile 32x32; BK=32; 3-stage cp.async; 36KB smem.
// Small tile => ~4x shorter CTA residence => step-chain kernels acquire SMs fast.
#define TILE_A 4096            // 64 rows x 64B
#define TILE_B 8192            // 128 rows x 64B
#define STAGE_BYTES 12288
#define NCHUNKS3 3

__global__ void __launch_bounds__(256)
logits_mma_kernel(const float* __restrict__ bout, float* __restrict__ out, int m_base) {
    __shared__ __align__(16) char sm[3 * STAGE_BYTES];   // 36 KB
    int tid  = threadIdx.x;
    int warp = tid >> 5, lane = tid & 31;
    int wm = warp & 1, wn = warp >> 1;
    int n0 = blockIdx.x * 128;            // vocab tile
    int m0 = m_base + blockIdx.y * 64;    // r' tile (64 rows)
    uint32_t sbase = smem_to_u32(sm);

    // ---- ldmatrix addressing (offsets within a stage)
    uint32_t aRow[2], aSwz[2];
    #pragma unroll
    for (int mi = 0; mi < 2; mi++) {
        int r = wm*32 + mi*16 + (lane & 15);
        aRow[mi] = (uint32_t)(r * 64);
        aSwz[mi] = (uint32_t)((r >> 1) & 3);
    }
    uint32_t aK = (uint32_t)(lane >> 4);
    uint32_t bRow[2], bSwz[2];
    #pragma unroll
    for (int nq = 0; nq < 2; nq++) {
        int r = wn*32 + nq*16 + (lane & 7) + ((lane >> 4) & 1)*8;
        bRow[nq] = (uint32_t)(TILE_A + r * 64);
        bSwz[nq] = (uint32_t)((r >> 1) & 3);
    }
    uint32_t bK = (uint32_t)((lane >> 3) & 1);

    float acc[2][4][4] = {};

    // ---- cp.async issue: 3 x 16B per thread (A 256 chunks + B 512 chunks)
    auto issue = [&](uint32_t dstoff, int kofs) {
        #pragma unroll
        for (int i = 0; i < 3; i++) {
            int id  = tid + i * 256;         // 0..767
            int isB = (id >= 256);
            int rem = isB ? (id - 256) : id;
            int row = rem >> 2;
            int h   = rem & 3;
            uint32_t so = (uint32_t)((isB ? TILE_A : 0) + row * 64 +
                                     ((h ^ ((row >> 1) & 3)) << 4));
            const __half* g = isB ? (g_Bh + (size_t)(n0 + row) * Kcat)
                                  : (g_Ah + (size_t)(m0 + row) * Kcat);
            CP_ASYNC16(dstoff + so, g + kofs + h * 8);
        }
    };

    issue(sbase, 0);                   CP_COMMIT();
    issue(sbase + STAGE_BYTES, 32);    CP_COMMIT();
    issue(sbase + 2*STAGE_BYTES, 64);  CP_COMMIT();

    int bufsel = 0;
    for (int s = 0; s < NCH; s++) {
        CP_WAIT2();
        __syncthreads();
        uint32_t stb = sbase + (uint32_t)bufsel * STAGE_BYTES;

        #pragma unroll
        for (int st = 0; st < 2; st++) {
            uint32_t bfr[2][4];
            #pragma unroll
            for (int nq = 0; nq < 2; nq++) {
                uint32_t c = ((uint32_t)(st*2) + bK) ^ bSwz[nq];
                ldsm4(bfr[nq][0], bfr[nq][1], bfr[nq][2], bfr[nq][3],
                      stb + bRow[nq] + (c << 4));
            }
            uint32_t af[2][4];
            #pragma unroll
            for (int mi = 0; mi < 2; mi++) {
                uint32_t c = ((uint32_t)(st*2) + aK) ^ aSwz[mi];
                ldsm4(af[mi][0], af[mi][1], af[mi][2], af[mi][3],
                      stb + aRow[mi] + (c << 4));
            }
            #pragma unroll
            for (int mi = 0; mi < 2; mi++) {
                mma16816(acc[mi][0], af[mi], &bfr[0][0]);
                mma16816(acc[mi][1], af[mi], &bfr[0][2]);
                mma16816(acc[mi][2], af[mi], &bfr[1][0]);
                mma16816(acc[mi][3], af[mi], &bfr[1][2]);
            }
        }
        __syncthreads();
        if (s + 3 < NCH) issue(stb, (s + 3) * 32);
        CP_COMMIT();
        bufsel = (bufsel == 2) ? 0 : bufsel + 1;
    }

    // ---- epilogue: r' -> (b, t) rows, add bias
    #pragma unroll
    for (int mi = 0; mi < 2; mi++) {
        int rp0 = m0 + wm*32 + mi*16 + (lane >> 2);
        int rp1 = rp0 + 8;
        int r0o = ((rp0 & 127) * Tt + (rp0 >> 7));   // b*T + t
        int r1o = ((rp1 & 127) * Tt + (rp1 >> 7));
        float* orow0 = out + (size_t)r0o * Vv;
        float* orow1 = out + (size_t)r1o * Vv;
        #pragma unroll
        for (int ni = 0; ni < 4; ni++) {
            int v = n0 + wn*32 + ni*8 + (lane & 3)*2;
            if (v < Vv) {
                float bv0 = bout[v];
                orow0[v] = acc[mi][ni][0] + bv0;
                orow1[v] = acc[mi][ni][2] + bv0;
            }
            if (v + 1 < Vv) {
                float bv1 = bout[v + 1];
                orow0[v+1] = acc[mi][ni][1] + bv1;
                orow1[v+1] = acc[mi][ni][3] + bv1;
            }
        }
    }
}

// ---------------- launch -------------------------------------------------------------
extern "C" void kernel_launch(void* const* d_in, const int* in_sizes, int n_in,
                              void* d_out, int out_size) {
    const float* img  = (const float*)d_in[0];
    const int*   ix   = (const int*)d_in[1];
    const float* Wh0  = (const float*)d_in[2];
    const float* bh0  = (const float*)d_in[3];
    const float* Wc0  = (const float*)d_in[4];
    const float* bc0  = (const float*)d_in[5];
    const float* Wkey = (const float*)d_in[6];
    const float* bkey = (const float*)d_in[7];
    const float* emb  = (const float*)d_in[8];
    const float* Wih  = (const float*)d_in[9];
    const float* bih  = (const float*)d_in[10];
    const float* Whh  = (const float*)d_in[11];
    const float* bhh  = (const float*)d_in[12];
    const float* Wout = (const float*)d_in[13];
    const float* bout = (const float*)d_in[14];

    float* out  = (float*)d_out;                       // logits [B,T,V]
    float* maps = out + (size_t)Bb * Tt * Vv;          // maps   [B,T,P]

    // plain streams + events (proven delta=0 under the allocation guards)
    cudaStream_t s2;
    cudaStreamCreateWithFlags(&s2, cudaStreamNonBlocking);
    cudaEvent_t eFork, eSlice[4], eJoin;
    cudaEventCreateWithFlags(&eFork, cudaEventDisableTiming);
    cudaEventCreateWithFlags(&eJoin, cudaEventDisableTiming);
    for (int i = 0; i < 4; i++) cudaEventCreateWithFlags(&eSlice[i], cudaEventDisableTiming);

    // fork: convB on side stream (independent of everything on main)
    cudaEventRecord(eFork, 0);
    cudaStreamWaitEvent(s2, eFork, 0);
    convB_kernel<<<Vpad, 256, 0, s2>>>(Wout);

    // main stream: prologue + step loop
    mean_kernel<<<(Bb*Cc)/8, 256>>>(img);
    hc0_kernel<<<Bb, 256>>>(Wh0, bh0, Wc0, bc0);
    emb_kernel<<<(Bb*Tt*Ee)/256, 256>>>(ix, emb);
    embh_kernel<<<(Bb*Tt*Ee)/256, 256>>>();            // emb segment of A, all rows
    keys_kernel<<<dim3(Uu/64, (Pp + 63)/64, Bb), 256>>>(Wkey, bkey, img);

    for (int t = 0; t < Tt; t++) {
        attn_kernel<<<Bb, 256>>>(t, img, maps);        // folds LSTM update of t-1
        if (t == 8 || t == 16 || t == 24) {
            // A rows for t' in [t-8, t) complete (h_{t-1} written by this attn)
            int sl = (t >> 3) - 1;
            cudaEventRecord(eSlice[sl], 0);
            cudaStreamWaitEvent(s2, eSlice[sl], 0);
            logits_mma_kernel<<<dim3(Vpad/128, 16), 256, 0, s2>>>(
                bout, out, (t - 8) * Bb);
        }
        gates_kernel<<<dim3(Gg/64, Bb/16), 256>>>(t, Wih, bih, Whh, bhh);
    }
    lstm_last_kernel<<<Bb, 256>>>();

    // final slice [24, 32) after lstm_last
    cudaEventRecord(eSlice[3], 0);
    cudaStreamWaitEvent(s2, eSlice[3], 0);
    logits_mma_kernel<<<dim3(Vpad/128, 16), 256, 0, s2>>>(bout, out, 24 * Bb);

    // join side stream back into main
    cudaEventRecord(eJoin, s2);
    cudaStreamWaitEvent(0, eJoin, 0);
}

// round 16
// speedup vs baseline: 1.2627x; 1.2627x over previous
#include <cuda_runtime.h>
#include <cuda_fp16.h>
#include <math.h>
#include <stdint.h>

#define Bb 128
#define Cc 512
#define Pp 196
#define Tt 32
#define Vv 10403
#define Ee 128
#define Uu 256
#define Gg 1024      // 4*U
#define Kcat 896     // C + E + U

#define Vpad 10496   // 82 * 128
#define NCH 28       // Kcat / 32 k-chunks

// packed fp32x2 FMA
#define FMA2(d, a, b) asm("fma.rn.f32x2 %0, %1, %2, %0;" : "+l"(d) : "l"(a), "l"(b))
#define PACK2(d, x)   asm("mov.b64 %0, {%1, %1};" : "=l"(d) : "f"(x))

__device__ __forceinline__ uint32_t smem_to_u32(const void* p) {
    uint32_t a;
    asm("{ .reg .u64 t; cvta.to.shared.u64 t, %1; cvt.u32.u64 %0, t; }" : "=r"(a) : "l"(p));
    return a;
}
__device__ __forceinline__ void ldsm4(uint32_t& r0, uint32_t& r1, uint32_t& r2, uint32_t& r3,
                                      uint32_t addr) {
    asm volatile("ldmatrix.sync.aligned.m8n8.x4.shared.b16 {%0,%1,%2,%3}, [%4];"
                 : "=r"(r0), "=r"(r1), "=r"(r2), "=r"(r3) : "r"(addr));
}
__device__ __forceinline__ void mma16816(float* d, const uint32_t* a, const uint32_t* b) {
    asm volatile("mma.sync.aligned.m16n8k16.row.col.f32.f16.f16.f32 "
                 "{%0,%1,%2,%3}, {%4,%5,%6,%7}, {%8,%9}, {%0,%1,%2,%3};"
                 : "+f"(d[0]), "+f"(d[1]), "+f"(d[2]), "+f"(d[3])
                 : "r"(a[0]), "r"(a[1]), "r"(a[2]), "r"(a[3]), "r"(b[0]), "r"(b[1]));
}
#define CP_ASYNC16(sm, g) \
    asm volatile("cp.async.cg.shared.global [%0], [%1], 16;" :: "r"(sm), "l"(g))
#define CP_COMMIT() asm volatile("cp.async.commit_group;")
#define CP_WAIT2()  asm volatile("cp.async.wait_group 2;")

// ---------------- scratch (device globals) -------------------------------------
__device__ float g_mean[Bb*Cc];
__device__ float g_keys[Bb*Pp*Uu];       // [B,P,U]
__device__ float g_xemb[Bb*Tt*Ee];       // [B,T,E]
__device__ float g_h[Bb*Uu];
__device__ float g_c[Bb*Uu];
__device__ float g_q[Bb*Uu];
__device__ float g_gates[Bb*Gg];
__device__ float g_attn[Bb*Tt*Cc];       // [B,T,C]
// A matrix in r' = t*128 + b order, fp16, filled by producers (no convA pass)
__device__ __half g_Ah[(size_t)Bb*Tt*Kcat];   // [4096, 896]
__device__ __half g_Bh[(size_t)Vpad*Kcat];    // [10496, 896]

// ---------------- mean over spatial positions -----------------------------------
__global__ void mean_kernel(const float* __restrict__ img) {
    int row  = blockIdx.x * 8 + (threadIdx.x >> 5);
    int lane = threadIdx.x & 31;
    const float* src = img + (size_t)row * Pp;
    float s = 0.f;
    for (int p = lane; p < Pp; p += 32) s += src[p];
    #pragma unroll
    for (int o = 16; o > 0; o >>= 1) s += __shfl_down_sync(0xffffffffu, s, o);
    if (lane == 0) g_mean[row] = s * (1.0f / 196.0f);
}

// ---------------- h0 / c0 init ---------------------------------------------------
__global__ void hc0_kernel(const float* __restrict__ Wh0, const float* __restrict__ bh0,
                           const float* __restrict__ Wc0, const float* __restrict__ bc0) {
    __shared__ float mf[Cc];
    int b = blockIdx.x, tid = threadIdx.x;
    mf[tid]       = g_mean[b*Cc + tid];
    mf[tid + 256] = g_mean[b*Cc + 256 + tid];
    __syncthreads();
    int u = tid;
    const float* wh = Wh0 + (size_t)u * Cc;
    const float* wc = Wc0 + (size_t)u * Cc;
    float ah = 0.f, ac = 0.f;
    #pragma unroll 4
    for (int c = 0; c < Cc; c++) { ah += mf[c]*wh[c]; ac += mf[c]*wc[c]; }
    float h0 = ah + bh0[u];
    float c0 = ac + bc0[u];
    g_h[b*Uu + u] = h0;
    g_c[b*Uu + u] = c0;
    g_q[b*Uu + u] = c0;
}

// ---------------- embedding gather (f32 staging + fp16 A segment, fused) ----------
__global__ void emb_kernel(const int* __restrict__ ix, const float* __restrict__ emb) {
    int idx = blockIdx.x * 256 + threadIdx.x;   // < B*T*E
    int r = idx >> 7, e = idx & 127;            // r = b*T + t
    float v = emb[(size_t)ix[r] * Ee + e];
    g_xemb[idx] = v;
    int b = r >> 5, t = r & 31;
    g_Ah[(size_t)(t*Bb + b) * Kcat + Cc + e] = __float2half(v);
}

// ---------------- Wout -> fp16, padded rows zero ----------------------------------
__global__ void convB_kernel(const float* __restrict__ Wout) {
    int v = blockIdx.x;
    int tid = threadIdx.x;
    __half* dst = g_Bh + (size_t)v * Kcat;
    if (v < Vv) {
        const float* src = Wout + (size_t)v * Kcat;
        for (int k = tid; k < Kcat; k += 256) dst[k] = __float2half(src[k]);
    } else {
        for (int k = tid; k < Kcat; k += 256) dst[k] = __float2half(0.f);
    }
}

// ---------------- keys[b,p,u] -----------------------------------------------------
__global__ void keys_kernel(const float* __restrict__ Wk, const float* __restrict__ bk,
                            const float* __restrict__ img) {
    int b  = blockIdx.z;
    int n0 = blockIdx.x * 64;   // u
    int m0 = blockIdx.y * 64;   // p
    __shared__ __align__(16) float sA[16][68];
    __shared__ __align__(16) float sB[16][68];
    int tid = threadIdx.x;
    int tx = tid & 15, ty = tid >> 4;
    unsigned long long accp[4][2] = {};
    const float* imgb = img + (size_t)b * Cc * Pp;
    for (int k0 = 0; k0 < Cc; k0 += 16) {
        {
            int k = tid >> 4, mg = tid & 15;
            int p = m0 + mg*4;
            float4 v = make_float4(0.f,0.f,0.f,0.f);
            if (p < Pp) v = *(const float4*)&imgb[(size_t)(k0+k)*Pp + p];
            *(float4*)&sA[k][mg*4] = v;
        }
        {
            int nn = tid & 63, kg = tid >> 6;
            float4 v = *(const float4*)&Wk[(size_t)(n0+nn)*Cc + k0 + kg*4];
            sB[kg*4+0][nn] = v.x; sB[kg*4+1][nn] = v.y;
            sB[kg*4+2][nn] = v.z; sB[kg*4+3][nn] = v.w;
        }
        __syncthreads();
        #pragma unroll
        for (int kk = 0; kk < 16; kk++) {
            float4 a4 = *(const float4*)&sA[kk][ty*4];
            ulonglong2 b2 = *(const ulonglong2*)&sB[kk][tx*4];
            float av[4] = {a4.x, a4.y, a4.z, a4.w};
            #pragma unroll
            for (int i = 0; i < 4; i++) {
                unsigned long long ap; PACK2(ap, av[i]);
                FMA2(accp[i][0], ap, b2.x);
                FMA2(accp[i][1], ap, b2.y);
            }
        }
        __syncthreads();
    }
    #pragma unroll
    for (int i = 0; i < 4; i++) {
        int p = m0 + ty*4 + i;
        if (p >= Pp) continue;
        float* orow = g_keys + ((size_t)b*Pp + p)*Uu;
        #pragma unroll
        for (int j = 0; j < 2; j++) {
            float2 f = *(float2*)&accp[i][j];
            int u = n0 + tx*4 + j*2;
            orow[u]   = f.x + bk[u];
            orow[u+1] = f.y + bk[u+1];
        }
    }
}

// ---------------- per-step: lstm(t-1) + attention (warp-shuffle reductions) -------
__global__ void attn_kernel(int t, const float* __restrict__ img, float* __restrict__ maps) {
    int b = blockIdx.x, tid = threadIdx.x;
    int lane = tid & 31, wid = tid >> 5;
    __shared__ float qs[Uu];
    __shared__ float redm[8];
    __shared__ float reds[8];
    __shared__ float ws[256];
    float q;
    if (t == 0) {
        q = g_q[b*Uu + tid];
    } else {
        const float* g = g_gates + b*Gg;
        float ig = g[tid], fg = g[tid+256], gg = g[tid+512], og = g[tid+768];
        float si = 1.f / (1.f + expf(-ig));
        float sf = 1.f / (1.f + expf(-fg));
        float so = 1.f / (1.f + expf(-og));
        float cn = sf * g_c[b*Uu + tid] + si * tanhf(gg);
        float hn = so * tanhf(cn);
        g_c[b*Uu + tid] = cn;
        g_h[b*Uu + tid] = hn;
        g_Ah[(size_t)((t-1)*Bb + b)*Kcat + (Cc + Ee) + tid] = __float2half(hn);
        q = hn;
    }
    qs[tid] = q;
    __syncthreads();
    float s = -INFINITY;
    if (tid < Pp) {
        const float4* kb = (const float4*)(g_keys + ((size_t)b*Pp + tid)*Uu);
        float acc = 0.f;
        #pragma unroll 8
        for (int u4 = 0; u4 < Uu/4; u4++) {
            float4 kv = kb[u4];
            float4 qv = *(const float4*)&qs[u4*4];
            acc += kv.x*qv.x + kv.y*qv.y + kv.z*qv.z + kv.w*qv.w;
        }
        s = acc * 0.0625f;
    }
    // block max via warp shuffles + 8-wide smem combine
    float m = s;
    #pragma unroll
    for (int o = 16; o > 0; o >>= 1) m = fmaxf(m, __shfl_xor_sync(0xffffffffu, m, o));
    if (lane == 0) redm[wid] = m;
    __syncthreads();
    float mx = fmaxf(fmaxf(fmaxf(redm[0], redm[1]), fmaxf(redm[2], redm[3])),
                     fmaxf(fmaxf(redm[4], redm[5]), fmaxf(redm[6], redm[7])));
    float ex = (tid < Pp) ? expf(s - mx) : 0.f;
    float sm = ex;
    #pragma unroll
    for (int o = 16; o > 0; o >>= 1) sm += __shfl_xor_sync(0xffffffffu, sm, o);
    if (lane == 0) reds[wid] = sm;
    __syncthreads();
    float tot = (reds[0] + reds[1]) + (reds[2] + reds[3])
              + (reds[4] + reds[5]) + (reds[6] + reds[7]);
    float w = ex * (1.f / tot);
    ws[tid] = w;
    if (tid < Pp) maps[((size_t)b*Tt + t)*Pp + tid] = w;
    __syncthreads();
    // weighted sum: thread tid owns channels tid and tid+256
    {
        const float* r0 = img + ((size_t)b*Cc + tid)*Pp;
        const float* r1 = r0 + 256*(size_t)Pp;
        float a0 = 0.f, a1 = 0.f;
        #pragma unroll 7
        for (int p = 0; p < Pp; p += 4) {
            float4 w4 = *(const float4*)&ws[p];
            float4 x0 = *(const float4*)&r0[p];
            float4 x1 = *(const float4*)&r1[p];
            a0 += w4.x*x0.x + w4.y*x0.y + w4.z*x0.z + w4.w*x0.w;
            a1 += w4.x*x1.x + w4.y*x1.y + w4.z*x1.z + w4.w*x1.w;
        }
        float* arow = g_attn + ((size_t)b*Tt + t)*Cc;
        arow[tid]       = a0;
        arow[tid + 256] = a1;
        __half* ah = g_Ah + (size_t)(t*Bb + b)*Kcat;
        ah[tid]       = __float2half(a0);
        ah[tid + 256] = __float2half(a1);
    }
}

// ---------------- per-step gates GEMM ---------------------------------------------
__global__ void gates_kernel(int t, const float* __restrict__ Wih, const float* __restrict__ bih,
                             const float* __restrict__ Whh, const float* __restrict__ bhh) {
    int n0 = blockIdx.x * 64;
    int m0 = blockIdx.y * 16;
    __shared__ __align__(16) float sA[32][16];
    __shared__ float sB[64][33];
    int tid = threadIdx.x;
    int n  = tid & 63;
    int mB = (tid >> 6) * 4;
    unsigned long long accp[2] = {};
    for (int k0 = 0; k0 < Kcat; k0 += 32) {
        #pragma unroll
        for (int i = 0; i < 2; i++) {
            int id = tid + i*256;
            int mm = id & 15, k = (id >> 4) & 31;
            int gk = k0 + k, bb = m0 + mm;
            float v;
            if (gk < Ee)            v = g_xemb[(bb*Tt + t)*Ee + gk];
            else if (gk < Ee + Cc)  v = g_attn[((size_t)bb*Tt + t)*Cc + (gk - Ee)];
            else                    v = g_h[bb*Uu + (gk - Ee - Cc)];
            sA[k][mm] = v;
        }
        #pragma unroll
        for (int i = 0; i < 8; i++) {
            int id = tid + i*256;
            int nn = id >> 5, k = id & 31;
            int gk = k0 + k, j = n0 + nn;
            sB[nn][k] = (gk < Ee + Cc) ? Wih[(size_t)j*(Ee+Cc) + gk]
                                       : Whh[(size_t)j*Uu + (gk - Ee - Cc)];
        }
        __syncthreads();
        #pragma unroll
        for (int kk = 0; kk < 32; kk++) {
            ulonglong2 ap2 = *(const ulonglong2*)&sA[kk][mB];
            float bv = sB[n][kk];
            unsigned long long bp; PACK2(bp, bv);
            FMA2(accp[0], ap2.x, bp);
            FMA2(accp[1], ap2.y, bp);
        }
        __syncthreads();
    }
    int j = n0 + n;
    float bias = bih[j] + bhh[j];
    float2 f0 = *(float2*)&accp[0];
    float2 f1 = *(float2*)&accp[1];
    g_gates[(m0 + mB + 0)*Gg + j] = f0.x + bias;
    g_gates[(m0 + mB + 1)*Gg + j] = f0.y + bias;
    g_gates[(m0 + mB + 2)*Gg + j] = f1.x + bias;
    g_gates[(m0 + mB + 3)*Gg + j] = f1.y + bias;
}

// ---------------- final LSTM update (h_31, fp16 straight into A) -------------------
__global__ void lstm_last_kernel() {
    int b = blockIdx.x, u = threadIdx.x;
    const float* g = g_gates + b*Gg;
    float ig = g[u], fg = g[u+256], gg = g[u+512], og = g[u+768];
    float si = 1.f / (1.f + expf(-ig));
    float sf = 1.f / (1.f + expf(-fg));
    float so = 1.f / (1.f + expf(-og));
    float cn = sf * g_c[b*Uu + u] + si * tanhf(gg);
    float hn = so * tanhf(cn);
    g_Ah[(size_t)((Tt-1)*Bb + b)*Kcat + (Cc + Ee) + u] = __float2half(hn);
}

// ---------------- HMMA fp16 logits GEMM: CTA tile 128x128, 3-stage cp.async -------
// D[r', v] = Ah[r', 896] @ Bh[Vpad, 896]^T;  r' = t*128 + b.
// 8 warps (2m x 4n), warp tile 64x32, BK=32. 48KB static smem.
#define TILE_BYTES 8192
#define STAGE_BYTES 16384

__global__ void __launch_bounds__(256)
logits_mma_kernel(const float* __restrict__ bout, float* __restrict__ out, int m_base) {
    __shared__ __align__(16) char sm[3 * STAGE_BYTES];   // 48 KB
    int tid  = threadIdx.x;
    int warp = tid >> 5, lane = tid & 31;
    int wm = warp & 1, wn = warp >> 1;
    int n0 = blockIdx.x * 128;            // vocab tile
    int m0 = m_base + blockIdx.y * 128;   // r' tile
    uint32_t sbase = smem_to_u32(sm);

    uint32_t aRow[4], aSwz[4];
    #pragma unroll
    for (int mi = 0; mi < 4; mi++) {
        int r = wm*64 + mi*16 + (lane & 15);
        aRow[mi] = (uint32_t)(r * 64);
        aSwz[mi] = (uint32_t)((r >> 1) & 3);
    }
    uint32_t aK = (uint32_t)(lane >> 4);
    uint32_t bRow[2], bSwz[2];
    #pragma unroll
    for (int nq = 0; nq < 2; nq++) {
        int r = wn*32 + nq*16 + (lane & 7) + ((lane >> 4) & 1)*8;
        bRow[nq] = (uint32_t)(TILE_BYTES + r * 64);
        bSwz[nq] = (uint32_t)((r >> 1) & 3);
    }
    uint32_t bK = (uint32_t)((lane >> 3) & 1);

    float acc[4][4][4] = {};

    auto issue = [&](uint32_t dstoff, int kofs) {
        #pragma unroll
        for (int i = 0; i < 4; i++) {
            int id   = tid + i * 256;
            int tile = id >> 9;          // 0=A, 1=B
            int rem  = id & 511;
            int row  = rem >> 2;
            int h    = rem & 3;
            uint32_t so = (uint32_t)(tile * TILE_BYTES + row * 64 +
                                     ((h ^ ((row >> 1) & 3)) << 4));
            const __half* g = tile ? (g_Bh + (size_t)(n0 + row) * Kcat)
                                   : (g_Ah + (size_t)(m0 + row) * Kcat);
            CP_ASYNC16(dstoff + so, g + kofs + h * 8);
        }
    };

    issue(sbase, 0);                   CP_COMMIT();
    issue(sbase + STAGE_BYTES, 32);    CP_COMMIT();
    issue(sbase + 2*STAGE_BYTES, 64);  CP_COMMIT();

    int bufsel = 0;
    for (int s = 0; s < NCH; s++) {
        CP_WAIT2();
        __syncthreads();
        uint32_t stb = sbase + (uint32_t)bufsel * STAGE_BYTES;

        #pragma unroll
        for (int st = 0; st < 2; st++) {
            uint32_t bfr[2][4];
            #pragma unroll
            for (int nq = 0; nq < 2; nq++) {
                uint32_t c = ((uint32_t)(st*2) + bK) ^ bSwz[nq];
                ldsm4(bfr[nq][0], bfr[nq][1], bfr[nq][2], bfr[nq][3],
                      stb + bRow[nq] + (c << 4));
            }
            uint32_t af[4][4];
            #pragma unroll
            for (int mi = 0; mi < 4; mi++) {
                uint32_t c = ((uint32_t)(st*2) + aK) ^ aSwz[mi];
                ldsm4(af[mi][0], af[mi][1], af[mi][2], af[mi][3],
                      stb + aRow[mi] + (c << 4));
            }
            #pragma unroll
            for (int mi = 0; mi < 4; mi++) {
                mma16816(acc[mi][0], af[mi], &bfr[0][0]);
                mma16816(acc[mi][1], af[mi], &bfr[0][2]);
                mma16816(acc[mi][2], af[mi], &bfr[1][0]);
                mma16816(acc[mi][3], af[mi], &bfr[1][2]);
            }
        }
        __syncthreads();
        if (s + 3 < NCH) issue(stb, (s + 3) * 32);
        CP_COMMIT();
        bufsel = (bufsel == 2) ? 0 : bufsel + 1;
    }

    // ---- epilogue: r' -> (b, t) rows, add bias
    #pragma unroll
    for (int mi = 0; mi < 4; mi++) {
        int rp0 = m0 + wm*64 + mi*16 + (lane >> 2);
        int rp1 = rp0 + 8;
        int r0o = ((rp0 & 127) * Tt + (rp0 >> 7));   // b*T + t
        int r1o = ((rp1 & 127) * Tt + (rp1 >> 7));
        float* orow0 = out + (size_t)r0o * Vv;
        float* orow1 = out + (size_t)r1o * Vv;
        #pragma unroll
        for (int ni = 0; ni < 4; ni++) {
            int v = n0 + wn*32 + ni*8 + (lane & 3)*2;
            if (v < Vv) {
                float bv0 = bout[v];
                orow0[v] = acc[mi][ni][0] + bv0;
                orow1[v] = acc[mi][ni][2] + bv0;
            }
            if (v + 1 < Vv) {
                float bv1 = bout[v + 1];
                orow0[v+1] = acc[mi][ni][1] + bv1;
                orow1[v+1] = acc[mi][ni][3] + bv1;
            }
        }
    }
}

// ---------------- launch -------------------------------------------------------------
extern "C" void kernel_launch(void* const* d_in, const int* in_sizes, int n_in,
                              void* d_out, int out_size) {
    const float* img  = (const float*)d_in[0];
    const int*   ix   = (const int*)d_in[1];
    const float* Wh0  = (const float*)d_in[2];
    const float* bh0  = (const float*)d_in[3];
    const float* Wc0  = (const float*)d_in[4];
    const float* bc0  = (const float*)d_in[5];
    const float* Wkey = (const float*)d_in[6];
    const float* bkey = (const float*)d_in[7];
    const float* emb  = (const float*)d_in[8];
    const float* Wih  = (const float*)d_in[9];
    const float* bih  = (const float*)d_in[10];
    const float* Whh  = (const float*)d_in[11];
    const float* bhh  = (const float*)d_in[12];
    const float* Wout = (const float*)d_in[13];
    const float* bout = (const float*)d_in[14];

    float* out  = (float*)d_out;                       // logits [B,T,V]
    float* maps = out + (size_t)Bb * Tt * Vv;          // maps   [B,T,P]

    // plain streams + events (proven delta=0 under the allocation guards)
    cudaStream_t s2;
    cudaStreamCreateWithFlags(&s2, cudaStreamNonBlocking);
    cudaEvent_t eFork, eSlice[5], eJoin;
    cudaEventCreateWithFlags(&eFork, cudaEventDisableTiming);
    cudaEventCreateWithFlags(&eJoin, cudaEventDisableTiming);
    for (int i = 0; i < 5; i++) cudaEventCreateWithFlags(&eSlice[i], cudaEventDisableTiming);

    // fork: convB on side stream (independent of everything on main)
    cudaEventRecord(eFork, 0);
    cudaStreamWaitEvent(s2, eFork, 0);
    convB_kernel<<<Vpad, 256, 0, s2>>>(Wout);

    // main stream: prologue + step loop
    mean_kernel<<<(Bb*Cc)/8, 256>>>(img);
    hc0_kernel<<<Bb, 256>>>(Wh0, bh0, Wc0, bc0);
    emb_kernel<<<(Bb*Tt*Ee)/256, 256>>>(ix, emb);      // writes f32 + fp16 A segment
    keys_kernel<<<dim3(Uu/64, (Pp + 63)/64, Bb), 256>>>(Wkey, bkey, img);

    for (int t = 0; t < Tt; t++) {
        attn_kernel<<<Bb, 256>>>(t, img, maps);        // folds LSTM update of t-1
        if (t == 8 || t == 16 || t == 24) {
            // A rows for t' in [t-8, t) complete (h_{t-1} written by this attn)
            int sl = (t >> 3) - 1;
            cudaEventRecord(eSlice[sl], 0);
            cudaStreamWaitEvent(s2, eSlice[sl], 0);
            logits_mma_kernel<<<dim3(Vpad/128, 8), 256, 0, s2>>>(
                bout, out, (t - 8) * Bb);
        } else if (t == 28) {
            // A rows for t' in [24, 28) complete
            cudaEventRecord(eSlice[3], 0);
            cudaStreamWaitEvent(s2, eSlice[3], 0);
            logits_mma_kernel<<<dim3(Vpad/128, 4), 256, 0, s2>>>(
                bout, out, 24 * Bb);
        }
        gates_kernel<<<dim3(Gg/64, Bb/16), 256>>>(t, Wih, bih, Whh, bhh);
    }
    lstm_last_kernel<<<Bb, 256>>>();

    // final small tail: rows [28, 32) only (~half the previous exposed tail)
    cudaEventRecord(eSlice[4], 0);
    cudaStreamWaitEvent(s2, eSlice[4], 0);
    logits_mma_kernel<<<dim3(Vpad/128, 4), 256, 0, s2>>>(bout, out, 28 * Bb);

    // join side stream back into main
    cudaEventRecord(eJoin, s2);
    cudaStreamWaitEvent(0, eJoin, 0);
}

// round 17
// speedup vs baseline: 1.9702x; 1.5603x over previous
#include <cuda_runtime.h>
#include <cuda_fp16.h>
#include <math.h>
#include <stdint.h>

#define Bb 128
#define Cc 512
#define Pp 196
#define Tt 32
#define Vv 10403
#define Ee 128
#define Uu 256
#define Gg 1024      // 4*U
#define Kcat 896     // C + E + U

#define Vpad 10496   // 82 * 128
#define NCH 28       // Kcat / 32 k-chunks

// packed fp32x2 FMA
#define FMA2(d, a, b) asm("fma.rn.f32x2 %0, %1, %2, %0;" : "+l"(d) : "l"(a), "l"(b))
#define PACK2(d, x)   asm("mov.b64 %0, {%1, %1};" : "=l"(d) : "f"(x))

__device__ __forceinline__ uint32_t smem_to_u32(const void* p) {
    uint32_t a;
    asm("{ .reg .u64 t; cvta.to.shared.u64 t, %1; cvt.u32.u64 %0, t; }" : "=r"(a) : "l"(p));
    return a;
}
__device__ __forceinline__ void ldsm4(uint32_t& r0, uint32_t& r1, uint32_t& r2, uint32_t& r3,
                                      uint32_t addr) {
    asm volatile("ldmatrix.sync.aligned.m8n8.x4.shared.b16 {%0,%1,%2,%3}, [%4];"
                 : "=r"(r0), "=r"(r1), "=r"(r2), "=r"(r3) : "r"(addr));
}
__device__ __forceinline__ void mma16816(float* d, const uint32_t* a, const uint32_t* b) {
    asm volatile("mma.sync.aligned.m16n8k16.row.col.f32.f16.f16.f32 "
                 "{%0,%1,%2,%3}, {%4,%5,%6,%7}, {%8,%9}, {%0,%1,%2,%3};"
                 : "+f"(d[0]), "+f"(d[1]), "+f"(d[2]), "+f"(d[3])
                 : "r"(a[0]), "r"(a[1]), "r"(a[2]), "r"(a[3]), "r"(b[0]), "r"(b[1]));
}
#define CP_ASYNC16(sm, g) \
    asm volatile("cp.async.cg.shared.global [%0], [%1], 16;" :: "r"(sm), "l"(g))
#define CP_COMMIT() asm volatile("cp.async.commit_group;")
#define CP_WAIT2()  asm volatile("cp.async.wait_group 2;")

// ---------------- scratch (device globals) -------------------------------------
__device__ float g_mean[Bb*Cc];
__device__ float g_keys[Bb*Pp*Uu];       // [B,P,U]
__device__ float g_c[Bb*Uu];
__device__ float g_q[Bb*Uu];             // first query (= c0)
__device__ float g_gates[Bb*Gg];
__device__ __half g_hh[Bb*Uu];           // current h (fp16, gates A h-segment)
__device__ __half g_Ah[(size_t)Bb*Tt*Kcat];   // [4096, 896] r' = t*128 + b: [attn|emb|h_t]
__device__ __half g_Bh[(size_t)Vpad*Kcat];    // [10496, 896] W_out fp16
__device__ __half g_Wc[(size_t)Gg*Kcat];      // [1024, 896] gates weights, A-segment order
__device__ float g_bias[Gg];                  // bih + bhh

// ---------------- mean over spatial positions -----------------------------------
__global__ void mean_kernel(const float* __restrict__ img) {
    int row  = blockIdx.x * 8 + (threadIdx.x >> 5);
    int lane = threadIdx.x & 31;
    const float* src = img + (size_t)row * Pp;
    float s = 0.f;
    for (int p = lane; p < Pp; p += 32) s += src[p];
    #pragma unroll
    for (int o = 16; o > 0; o >>= 1) s += __shfl_down_sync(0xffffffffu, s, o);
    if (lane == 0) g_mean[row] = s * (1.0f / 196.0f);
}

// ---------------- h0 / c0 init ---------------------------------------------------
__global__ void hc0_kernel(const float* __restrict__ Wh0, const float* __restrict__ bh0,
                           const float* __restrict__ Wc0, const float* __restrict__ bc0) {
    __shared__ float mf[Cc];
    int b = blockIdx.x, tid = threadIdx.x;
    mf[tid]       = g_mean[b*Cc + tid];
    mf[tid + 256] = g_mean[b*Cc + 256 + tid];
    __syncthreads();
    int u = tid;
    const float* wh = Wh0 + (size_t)u * Cc;
    const float* wc = Wc0 + (size_t)u * Cc;
    float ah = 0.f, ac = 0.f;
    #pragma unroll 4
    for (int c = 0; c < Cc; c++) { ah += mf[c]*wh[c]; ac += mf[c]*wc[c]; }
    float h0 = ah + bh0[u];
    float c0 = ac + bc0[u];
    g_c[b*Uu + u] = c0;
    g_q[b*Uu + u] = c0;                       // reference: first query is c0
    g_hh[b*Uu + u] = __float2half(h0);        // gates_0 reads h0
}

// ---------------- embedding gather -> fp16 A segment ------------------------------
__global__ void emb_kernel(const int* __restrict__ ix, const float* __restrict__ emb) {
    int idx = blockIdx.x * 256 + threadIdx.x;   // < B*T*E
    int r = idx >> 7, e = idx & 127;            // r = b*T + t
    float v = emb[(size_t)ix[r] * Ee + e];
    int b = r >> 5, t = r & 31;
    g_Ah[(size_t)(t*Bb + b) * Kcat + Cc + e] = __float2half(v);
}

// ---------------- Wout -> fp16, padded rows zero ----------------------------------
__global__ void convB_kernel(const float* __restrict__ Wout) {
    int v = blockIdx.x;
    int tid = threadIdx.x;
    __half* dst = g_Bh + (size_t)v * Kcat;
    if (v < Vv) {
        const float* src = Wout + (size_t)v * Kcat;
        for (int k = tid; k < Kcat; k += 256) dst[k] = __float2half(src[k]);
    } else {
        for (int k = tid; k < Kcat; k += 256) dst[k] = __float2half(0.f);
    }
}

// ---------------- gates weights -> fp16, A-segment order [attn|emb|h] -------------
__global__ void convW_kernel(const float* __restrict__ Wih, const float* __restrict__ bih,
                             const float* __restrict__ Whh, const float* __restrict__ bhh) {
    int j = blockIdx.x;          // < 1024
    int tid = threadIdx.x;       // 128
    __half* dst = g_Wc + (size_t)j * Kcat;
    for (int k = tid; k < Kcat; k += 128) {
        float v;
        if (k < Cc)            v = Wih[(size_t)j*(Ee+Cc) + Ee + k];        // attn cols
        else if (k < Cc + Ee)  v = Wih[(size_t)j*(Ee+Cc) + (k - Cc)];      // emb cols
        else                   v = Whh[(size_t)j*Uu + (k - Cc - Ee)];      // h cols
        dst[k] = __float2half(v);
    }
    if (tid == 0) g_bias[j] = bih[j] + bhh[j];
}

// ---------------- keys[b,p,u] -----------------------------------------------------
__global__ void keys_kernel(const float* __restrict__ Wk, const float* __restrict__ bk,
                            const float* __restrict__ img) {
    int b  = blockIdx.z;
    int n0 = blockIdx.x * 64;   // u
    int m0 = blockIdx.y * 64;   // p
    __shared__ __align__(16) float sA[16][68];
    __shared__ __align__(16) float sB[16][68];
    int tid = threadIdx.x;
    int tx = tid & 15, ty = tid >> 4;
    unsigned long long accp[4][2] = {};
    const float* imgb = img + (size_t)b * Cc * Pp;
    for (int k0 = 0; k0 < Cc; k0 += 16) {
        {
            int k = tid >> 4, mg = tid & 15;
            int p = m0 + mg*4;
            float4 v = make_float4(0.f,0.f,0.f,0.f);
            if (p < Pp) v = *(const float4*)&imgb[(size_t)(k0+k)*Pp + p];
            *(float4*)&sA[k][mg*4] = v;
        }
        {
            int nn = tid & 63, kg = tid >> 6;
            float4 v = *(const float4*)&Wk[(size_t)(n0+nn)*Cc + k0 + kg*4];
            sB[kg*4+0][nn] = v.x; sB[kg*4+1][nn] = v.y;
            sB[kg*4+2][nn] = v.z; sB[kg*4+3][nn] = v.w;
        }
        __syncthreads();
        #pragma unroll
        for (int kk = 0; kk < 16; kk++) {
            float4 a4 = *(const float4*)&sA[kk][ty*4];
            ulonglong2 b2 = *(const ulonglong2*)&sB[kk][tx*4];
            float av[4] = {a4.x, a4.y, a4.z, a4.w};
            #pragma unroll
            for (int i = 0; i < 4; i++) {
                unsigned long long ap; PACK2(ap, av[i]);
                FMA2(accp[i][0], ap, b2.x);
                FMA2(accp[i][1], ap, b2.y);
            }
        }
        __syncthreads();
    }
    #pragma unroll
    for (int i = 0; i < 4; i++) {
        int p = m0 + ty*4 + i;
        if (p >= Pp) continue;
        float* orow = g_keys + ((size_t)b*Pp + p)*Uu;
        #pragma unroll
        for (int j = 0; j < 2; j++) {
            float2 f = *(float2*)&accp[i][j];
            int u = n0 + tx*4 + j*2;
            orow[u]   = f.x + bk[u];
            orow[u+1] = f.y + bk[u+1];
        }
    }
}

// ---------------- per-step: lstm(t-1) + attention (warp-shuffle reductions) -------
__global__ void attn_kernel(int t, const float* __restrict__ img, float* __restrict__ maps) {
    int b = blockIdx.x, tid = threadIdx.x;
    int lane = tid & 31, wid = tid >> 5;
    __shared__ float qs[Uu];
    __shared__ float redm[8];
    __shared__ float reds[8];
    __shared__ float ws[256];
    float q;
    if (t == 0) {
        q = g_q[b*Uu + tid];
    } else {
        const float* g = g_gates + b*Gg;
        float ig = g[tid], fg = g[tid+256], gg = g[tid+512], og = g[tid+768];
        float si = 1.f / (1.f + expf(-ig));
        float sf = 1.f / (1.f + expf(-fg));
        float so = 1.f / (1.f + expf(-og));
        float cn = sf * g_c[b*Uu + tid] + si * tanhf(gg);
        float hn = so * tanhf(cn);
        g_c[b*Uu + tid] = cn;
        __half hh = __float2half(hn);
        g_hh[b*Uu + tid] = hh;                                            // gates_t h
        g_Ah[(size_t)((t-1)*Bb + b)*Kcat + (Cc + Ee) + tid] = hh;         // logits A
        q = hn;
    }
    qs[tid] = q;
    __syncthreads();
    float s = -INFINITY;
    if (tid < Pp) {
        const float4* kb = (const float4*)(g_keys + ((size_t)b*Pp + tid)*Uu);
        float acc = 0.f;
        #pragma unroll 8
        for (int u4 = 0; u4 < Uu/4; u4++) {
            float4 kv = kb[u4];
            float4 qv = *(const float4*)&qs[u4*4];
            acc += kv.x*qv.x + kv.y*qv.y + kv.z*qv.z + kv.w*qv.w;
        }
        s = acc * 0.0625f;
    }
    float m = s;
    #pragma unroll
    for (int o = 16; o > 0; o >>= 1) m = fmaxf(m, __shfl_xor_sync(0xffffffffu, m, o));
    if (lane == 0) redm[wid] = m;
    __syncthreads();
    float mx = fmaxf(fmaxf(fmaxf(redm[0], redm[1]), fmaxf(redm[2], redm[3])),
                     fmaxf(fmaxf(redm[4], redm[5]), fmaxf(redm[6], redm[7])));
    float ex = (tid < Pp) ? expf(s - mx) : 0.f;
    float sm = ex;
    #pragma unroll
    for (int o = 16; o > 0; o >>= 1) sm += __shfl_xor_sync(0xffffffffu, sm, o);
    if (lane == 0) reds[wid] = sm;
    __syncthreads();
    float tot = (reds[0] + reds[1]) + (reds[2] + reds[3])
              + (reds[4] + reds[5]) + (reds[6] + reds[7]);
    float w = ex * (1.f / tot);
    ws[tid] = w;
    if (tid < Pp) maps[((size_t)b*Tt + t)*Pp + tid] = w;
    __syncthreads();
    // weighted sum: thread tid owns channels tid and tid+256 (fp16 out only)
    {
        const float* r0 = img + ((size_t)b*Cc + tid)*Pp;
        const float* r1 = r0 + 256*(size_t)Pp;
        float a0 = 0.f, a1 = 0.f;
        #pragma unroll 7
        for (int p = 0; p < Pp; p += 4) {
            float4 w4 = *(const float4*)&ws[p];
            float4 x0 = *(const float4*)&r0[p];
            float4 x1 = *(const float4*)&r1[p];
            a0 += w4.x*x0.x + w4.y*x0.y + w4.z*x0.z + w4.w*x0.w;
            a1 += w4.x*x1.x + w4.y*x1.y + w4.z*x1.z + w4.w*x1.w;
        }
        __half* ah = g_Ah + (size_t)(t*Bb + b)*Kcat;
        ah[tid]       = __float2half(a0);
        ah[tid + 256] = __float2half(a1);
    }
}

// ---------------- per-step gates GEMM: HMMA fp16, 32x128 tiles --------------------
// g_gates[b, j] = A[b, 896] @ g_Wc[j, 896]^T + bias[j]
// A row b: k<640 from g_Ah[t*128+b], k>=640 from g_hh[b] (h_{t-1}).
// grid (8, 4), 128 threads (4 warps: warp tile 32x32), 3-stage cp.async, 30KB smem.
#define GA_BYTES 2048
#define GSTAGE 10240

__global__ void __launch_bounds__(128)
gates_mma_kernel(int t) {
    __shared__ __align__(16) char sm[3 * GSTAGE];
    int tid  = threadIdx.x;
    int warp = tid >> 5, lane = tid & 31;
    int n0 = blockIdx.x * 128;    // j tile
    int m0 = blockIdx.y * 32;     // batch tile
    uint32_t sbase = smem_to_u32(sm);

    uint32_t aRow[2], aSwz[2];
    #pragma unroll
    for (int mi = 0; mi < 2; mi++) {
        int r = mi*16 + (lane & 15);
        aRow[mi] = (uint32_t)(r * 64);
        aSwz[mi] = (uint32_t)((r >> 1) & 3);
    }
    uint32_t aK = (uint32_t)(lane >> 4);
    uint32_t bRow[2], bSwz[2];
    #pragma unroll
    for (int nq = 0; nq < 2; nq++) {
        int r = warp*32 + nq*16 + (lane & 7) + ((lane >> 4) & 1)*8;
        bRow[nq] = (uint32_t)(GA_BYTES + r * 64);
        bSwz[nq] = (uint32_t)((r >> 1) & 3);
    }
    uint32_t bK = (uint32_t)((lane >> 3) & 1);

    float acc[2][4][4] = {};

    auto issue = [&](uint32_t dstoff, int c) {
        int kofs = c * 32;
        #pragma unroll
        for (int i = 0; i < 5; i++) {
            int id = tid + i * 128;          // 0..639
            if (id < 128) {
                int row = id >> 2, h = id & 3;
                uint32_t so = (uint32_t)(row * 64 + ((h ^ ((row >> 1) & 3)) << 4));
                const __half* g = (c < 20)
                    ? (g_Ah + (size_t)(t*Bb + m0 + row) * Kcat + kofs)
                    : (g_hh + (m0 + row) * Uu + (kofs - 640));
                CP_ASYNC16(dstoff + so, g + h * 8);
            } else {
                int rem = id - 128;
                int row = rem >> 2, h = rem & 3;
                uint32_t so = (uint32_t)(GA_BYTES + row * 64 +
                                         ((h ^ ((row >> 1) & 3)) << 4));
                CP_ASYNC16(dstoff + so, g_Wc + (size_t)(n0 + row) * Kcat + kofs + h * 8);
            }
        }
    };

    issue(sbase, 0);              CP_COMMIT();
    issue(sbase + GSTAGE, 1);     CP_COMMIT();
    issue(sbase + 2*GSTAGE, 2);   CP_COMMIT();

    int bufsel = 0;
    for (int s = 0; s < NCH; s++) {
        CP_WAIT2();
        __syncthreads();
        uint32_t stb = sbase + (uint32_t)bufsel * GSTAGE;
        #pragma unroll
        for (int st = 0; st < 2; st++) {
            uint32_t bfr[2][4];
            #pragma unroll
            for (int nq = 0; nq < 2; nq++) {
                uint32_t c = ((uint32_t)(st*2) + bK) ^ bSwz[nq];
                ldsm4(bfr[nq][0], bfr[nq][1], bfr[nq][2], bfr[nq][3],
                      stb + bRow[nq] + (c << 4));
            }
            uint32_t af[2][4];
            #pragma unroll
            for (int mi = 0; mi < 2; mi++) {
                uint32_t c = ((uint32_t)(st*2) + aK) ^ aSwz[mi];
                ldsm4(af[mi][0], af[mi][1], af[mi][2], af[mi][3],
                      stb + aRow[mi] + (c << 4));
            }
            #pragma unroll
            for (int mi = 0; mi < 2; mi++) {
                mma16816(acc[mi][0], af[mi], &bfr[0][0]);
                mma16816(acc[mi][1], af[mi], &bfr[0][2]);
                mma16816(acc[mi][2], af[mi], &bfr[1][0]);
                mma16816(acc[mi][3], af[mi], &bfr[1][2]);
            }
        }
        __syncthreads();
        if (s + 3 < NCH) issue(stb, s + 3);
        CP_COMMIT();
        bufsel = (bufsel == 2) ? 0 : bufsel + 1;
    }

    #pragma unroll
    for (int mi = 0; mi < 2; mi++) {
        int b0 = m0 + mi*16 + (lane >> 2);
        int b1 = b0 + 8;
        #pragma unroll
        for (int ni = 0; ni < 4; ni++) {
            int j = n0 + warp*32 + ni*8 + (lane & 3)*2;
            float bi0 = g_bias[j], bi1 = g_bias[j+1];
            g_gates[b0*Gg + j]     = acc[mi][ni][0] + bi0;
            g_gates[b0*Gg + j + 1] = acc[mi][ni][1] + bi1;
            g_gates[b1*Gg + j]     = acc[mi][ni][2] + bi0;
            g_gates[b1*Gg + j + 1] = acc[mi][ni][3] + bi1;
        }
    }
}

// ---------------- final LSTM update (h_31, fp16 straight into A) -------------------
__global__ void lstm_last_kernel() {
    int b = blockIdx.x, u = threadIdx.x;
    const float* g = g_gates + b*Gg;
    float ig = g[u], fg = g[u+256], gg = g[u+512], og = g[u+768];
    float si = 1.f / (1.f + expf(-ig));
    float sf = 1.f / (1.f + expf(-fg));
    float so = 1.f / (1.f + expf(-og));
    float cn = sf * g_c[b*Uu + u] + si * tanhf(gg);
    float hn = so * tanhf(cn);
    g_Ah[(size_t)((Tt-1)*Bb + b)*Kcat + (Cc + Ee) + u] = __float2half(hn);
}

// ---------------- HMMA fp16 logits GEMM: CTA tile 128x128, 3-stage cp.async -------
#define TILE_BYTES 8192
#define STAGE_BYTES 16384

__global__ void __launch_bounds__(256)
logits_mma_kernel(const float* __restrict__ bout, float* __restrict__ out, int m_base) {
    __shared__ __align__(16) char sm[3 * STAGE_BYTES];   // 48 KB
    int tid  = threadIdx.x;
    int warp = tid >> 5, lane = tid & 31;
    int wm = warp & 1, wn = warp >> 1;
    int n0 = blockIdx.x * 128;
    int m0 = m_base + blockIdx.y * 128;
    uint32_t sbase = smem_to_u32(sm);

    uint32_t aRow[4], aSwz[4];
    #pragma unroll
    for (int mi = 0; mi < 4; mi++) {
        int r = wm*64 + mi*16 + (lane & 15);
        aRow[mi] = (uint32_t)(r * 64);
        aSwz[mi] = (uint32_t)((r >> 1) & 3);
    }
    uint32_t aK = (uint32_t)(lane >> 4);
    uint32_t bRow[2], bSwz[2];
    #pragma unroll
    for (int nq = 0; nq < 2; nq++) {
        int r = wn*32 + nq*16 + (lane & 7) + ((lane >> 4) & 1)*8;
        bRow[nq] = (uint32_t)(TILE_BYTES + r * 64);
        bSwz[nq] = (uint32_t)((r >> 1) & 3);
    }
    uint32_t bK = (uint32_t)((lane >> 3) & 1);

    float acc[4][4][4] = {};

    auto issue = [&](uint32_t dstoff, int kofs) {
        #pragma unroll
        for (int i = 0; i < 4; i++) {
            int id   = tid + i * 256;
            int tile = id >> 9;
            int rem  = id & 511;
            int row  = rem >> 2;
            int h    = rem & 3;
            uint32_t so = (uint32_t)(tile * TILE_BYTES + row * 64 +
                                     ((h ^ ((row >> 1) & 3)) << 4));
            const __half* g = tile ? (g_Bh + (size_t)(n0 + row) * Kcat)
                                   : (g_Ah + (size_t)(m0 + row) * Kcat);
            CP_ASYNC16(dstoff + so, g + kofs + h * 8);
        }
    };

    issue(sbase, 0);                   CP_COMMIT();
    issue(sbase + STAGE_BYTES, 32);    CP_COMMIT();
    issue(sbase + 2*STAGE_BYTES, 64);  CP_COMMIT();

    int bufsel = 0;
    for (int s = 0; s < NCH; s++) {
        CP_WAIT2();
        __syncthreads();
        uint32_t stb = sbase + (uint32_t)bufsel * STAGE_BYTES;

        #pragma unroll
        for (int st = 0; st < 2; st++) {
            uint32_t bfr[2][4];
            #pragma unroll
            for (int nq = 0; nq < 2; nq++) {
                uint32_t c = ((uint32_t)(st*2) + bK) ^ bSwz[nq];
                ldsm4(bfr[nq][0], bfr[nq][1], bfr[nq][2], bfr[nq][3],
                      stb + bRow[nq] + (c << 4));
            }
            uint32_t af[4][4];
            #pragma unroll
            for (int mi = 0; mi < 4; mi++) {
                uint32_t c = ((uint32_t)(st*2) + aK) ^ aSwz[mi];
                ldsm4(af[mi][0], af[mi][1], af[mi][2], af[mi][3],
                      stb + aRow[mi] + (c << 4));
            }
            #pragma unroll
            for (int mi = 0; mi < 4; mi++) {
                mma16816(acc[mi][0], af[mi], &bfr[0][0]);
                mma16816(acc[mi][1], af[mi], &bfr[0][2]);
                mma16816(acc[mi][2], af[mi], &bfr[1][0]);
                mma16816(acc[mi][3], af[mi], &bfr[1][2]);
            }
        }
        __syncthreads();
        if (s + 3 < NCH) issue(stb, (s + 3) * 32);
        CP_COMMIT();
        bufsel = (bufsel == 2) ? 0 : bufsel + 1;
    }

    #pragma unroll
    for (int mi = 0; mi < 4; mi++) {
        int rp0 = m0 + wm*64 + mi*16 + (lane >> 2);
        int rp1 = rp0 + 8;
        int r0o = ((rp0 & 127) * Tt + (rp0 >> 7));
        int r1o = ((rp1 & 127) * Tt + (rp1 >> 7));
        float* orow0 = out + (size_t)r0o * Vv;
        float* orow1 = out + (size_t)r1o * Vv;
        #pragma unroll
        for (int ni = 0; ni < 4; ni++) {
            int v = n0 + wn*32 + ni*8 + (lane & 3)*2;
            if (v < Vv) {
                float bv0 = bout[v];
                orow0[v] = acc[mi][ni][0] + bv0;
                orow1[v] = acc[mi][ni][2] + bv0;
            }
            if (v + 1 < Vv) {
                float bv1 = bout[v + 1];
                orow0[v+1] = acc[mi][ni][1] + bv1;
                orow1[v+1] = acc[mi][ni][3] + bv1;
            }
        }
    }
}

// ---------------- launch -------------------------------------------------------------
extern "C" void kernel_launch(void* const* d_in, const int* in_sizes, int n_in,
                              void* d_out, int out_size) {
    const float* img  = (const float*)d_in[0];
    const int*   ix   = (const int*)d_in[1];
    const float* Wh0  = (const float*)d_in[2];
    const float* bh0  = (const float*)d_in[3];
    const float* Wc0  = (const float*)d_in[4];
    const float* bc0  = (const float*)d_in[5];
    const float* Wkey = (const float*)d_in[6];
    const float* bkey = (const float*)d_in[7];
    const float* emb  = (const float*)d_in[8];
    const float* Wih  = (const float*)d_in[9];
    const float* bih  = (const float*)d_in[10];
    const float* Whh  = (const float*)d_in[11];
    const float* bhh  = (const float*)d_in[12];
    const float* Wout = (const float*)d_in[13];
    const float* bout = (const float*)d_in[14];

    float* out  = (float*)d_out;                       // logits [B,T,V]
    float* maps = out + (size_t)Bb * Tt * Vv;          // maps   [B,T,P]

    cudaStream_t s2;
    cudaStreamCreateWithFlags(&s2, cudaStreamNonBlocking);
    cudaEvent_t eFork, eSlice[5], eJoin;
    cudaEventCreateWithFlags(&eFork, cudaEventDisableTiming);
    cudaEventCreateWithFlags(&eJoin, cudaEventDisableTiming);
    for (int i = 0; i < 5; i++) cudaEventCreateWithFlags(&eSlice[i], cudaEventDisableTiming);

    // fork: convB on side stream (independent of everything on main)
    cudaEventRecord(eFork, 0);
    cudaStreamWaitEvent(s2, eFork, 0);
    convB_kernel<<<Vpad, 256, 0, s2>>>(Wout);

    // main stream: prologue + step loop
    mean_kernel<<<(Bb*Cc)/8, 256>>>(img);
    hc0_kernel<<<Bb, 256>>>(Wh0, bh0, Wc0, bc0);
    emb_kernel<<<(Bb*Tt*Ee)/256, 256>>>(ix, emb);
    convW_kernel<<<Gg, 128>>>(Wih, bih, Whh, bhh);
    keys_kernel<<<dim3(Uu/64, (Pp + 63)/64, Bb), 256>>>(Wkey, bkey, img);

    for (int t = 0; t < Tt; t++) {
        attn_kernel<<<Bb, 256>>>(t, img, maps);        // folds LSTM update of t-1
        if (t == 8 || t == 16 || t == 24) {
            int sl = (t >> 3) - 1;
            cudaEventRecord(eSlice[sl], 0);
            cudaStreamWaitEvent(s2, eSlice[sl], 0);
            logits_mma_kernel<<<dim3(Vpad/128, 8), 256, 0, s2>>>(
                bout, out, (t - 8) * Bb);
        } else if (t == 28) {
            cudaEventRecord(eSlice[3], 0);
            cudaStreamWaitEvent(s2, eSlice[3], 0);
            logits_mma_kernel<<<dim3(Vpad/128, 4), 256, 0, s2>>>(
                bout, out, 24 * Bb);
        }
        gates_mma_kernel<<<dim3(8, 4), 128>>>(t);
    }
    lstm_last_kernel<<<Bb, 256>>>();

    // final small tail: rows [28, 32)
    cudaEventRecord(eSlice[4], 0);
    cudaStreamWaitEvent(s2, eSlice[4], 0);
    logits_mma_kernel<<<dim3(Vpad/128, 4), 256, 0, s2>>>(bout, out, 28 * Bb);

    // join side stream back into main
    cudaEventRecord(eJoin, s2);
    cudaStreamWaitEvent(0, eJoin, 0);
}